// round 3
// baseline (speedup 1.0000x reference)
#include <cuda_runtime.h>
#include <math.h>

#define EPS_BN 1e-5f

// ---- problem constants ----
#define B_EP   32
#define NS     200
#define NQ     100
#define NWAY   20
#define CIN    8
#define LIN    512
#define FDIM   128
#define NSUP   (B_EP*NS)     // 6400
#define NQRY   (B_EP*NQ)     // 3200
#define NTOT   (NSUP+NQRY)   // 9600
#define NT     512

typedef unsigned long long ull;

__device__ float g_feat[NTOT*FDIM];
__device__ float g_proto[B_EP*NWAY*FDIM];

// ---- shared memory layout (float offsets) ----
#define OFF_X0   0            // 8 x 516   = 4128
#define OFF_S1   4128         // 32 x 260  = 8320   (region reused by w3)
#define OFF_W3   0            // 24576 floats (12288 pairs)
#define OFF_S2   24576        // 64 x 132  = 8448
#define OFF_W2   33024        // 6144
#define OFF_W1   39168        // 768
#define OFF_SC1  39936        // 32 (pair-adjacent channels are adjacent floats)
#define OFF_BI1  39968
#define OFF_SC2  40000
#define OFF_BI2  40064
#define OFF_SC3  40128
#define OFF_BI3  40256
#define OFF_SCF  40384
#define OFF_BIF  40512
#define OFF_F3   40640
#define OFF_RED  40768
#define SMEM_FLOATS 40800
#define SMEM_BYTES  (SMEM_FLOATS*4)

// ---- packed f32x2 helpers ----
__device__ __forceinline__ ull ffma2(ull a, ull b, ull c) {
    ull d;
    asm("fma.rn.f32x2 %0, %1, %2, %3;" : "=l"(d) : "l"(a), "l"(b), "l"(c));
    return d;
}
__device__ __forceinline__ ull splat2(float x) {
    ull d;
    asm("mov.b64 %0, {%1, %1};" : "=l"(d) : "f"(x));
    return d;
}
__device__ __forceinline__ void unpack2(ull v, float& lo, float& hi) {
    asm("mov.b64 {%0, %1}, %2;" : "=f"(lo), "=f"(hi) : "l"(v));
}

// Stage conv weights W[OC][IC][3] into smem as channel-PAIR interleaved float2.
template<int IC3, int TOT>
__device__ __forceinline__ void stage_w_pairs(const float* __restrict__ W,
                                              float* __restrict__ Wp, int t)
{
    for (int f = t; f < TOT; f += NT) {
        int o = f / IC3, r = f - o*IC3;
        Wp[(o >> 1)*(2*IC3) + 2*r + (o & 1)] = __ldg(W + f);
    }
}

// Fused conv1d(k=3,pad=1)+BN+ReLU+maxpool2, packed f32x2.
// Tile: 4 output channels (2 pairs) x 8 conv positions (-> 4 pooled) per thread.
// One pass: (OC/4)*Q == NT.  Q = L/8.
// MEAN variant (stage 3): Q==16, reduce over 16-lane halves.
template<int IC, int OC, int Q, int XRS, bool MEAN>
__device__ __forceinline__ void conv_stage8(const float* __restrict__ X,
                                            const ull* __restrict__ Wp,
                                            const ull* __restrict__ scp,
                                            const ull* __restrict__ bip,
                                            float* __restrict__ Y, int YRS,
                                            float* __restrict__ f3, int t)
{
    constexpr int IC3 = IC*3;
    static_assert((OC/4)*Q == NT, "one pass");
    const int q  = t % Q;        // consecutive lanes -> contiguous x
    const int ot = t / Q;        // uniform per warp (or half-warp when Q==16)
    const int l0 = 8*q, o0 = 4*ot;

    ull acc[2][8];
    #pragma unroll
    for (int p = 0; p < 2; ++p)
        #pragma unroll
        for (int j = 0; j < 8; ++j) acc[p][j] = 0ull;

    const ull* w0r = Wp + (o0 >> 1)*IC3;   // pair (o0, o0+1)
    const ull* w1r = w0r + IC3;            // pair (o0+2, o0+3)
    const float* xcol = X + l0;
    #pragma unroll 4
    for (int i = 0; i < IC; ++i) {
        const float* xr = xcol + i*XRS;
        float4 xa = *reinterpret_cast<const float4*>(xr);
        float4 xb = *reinterpret_cast<const float4*>(xr + 4);
        float2 xc = *reinterpret_cast<const float2*>(xr + 8);
        ull xs[10];
        xs[0]=splat2(xa.x); xs[1]=splat2(xa.y); xs[2]=splat2(xa.z); xs[3]=splat2(xa.w);
        xs[4]=splat2(xb.x); xs[5]=splat2(xb.y); xs[6]=splat2(xb.z); xs[7]=splat2(xb.w);
        xs[8]=splat2(xc.x); xs[9]=splat2(xc.y);
        ull wa0 = w0r[3*i], wa1 = w0r[3*i+1], wa2 = w0r[3*i+2];
        ull wb0 = w1r[3*i], wb1 = w1r[3*i+1], wb2 = w1r[3*i+2];
        #pragma unroll
        for (int j = 0; j < 8; ++j) {
            acc[0][j] = ffma2(wa2, xs[j+2], ffma2(wa1, xs[j+1], ffma2(wa0, xs[j], acc[0][j])));
            acc[1][j] = ffma2(wb2, xs[j+2], ffma2(wb1, xs[j+1], ffma2(wb0, xs[j], acc[1][j])));
        }
    }

    #pragma unroll
    for (int p = 0; p < 2; ++p) {
        int pr = (o0 >> 1) + p;            // channel pair index (cA=2pr, cB=2pr+1)
        ull s2 = scp[pr], b2 = bip[pr];
        float a[8], b[8];
        #pragma unroll
        for (int j = 0; j < 8; ++j) {
            ull y = ffma2(acc[p][j], s2, b2);   // packed BN
            unpack2(y, a[j], b[j]);
        }
        float pA0 = fmaxf(fmaxf(a[0],0.f), fmaxf(a[1],0.f));
        float pA1 = fmaxf(fmaxf(a[2],0.f), fmaxf(a[3],0.f));
        float pA2 = fmaxf(fmaxf(a[4],0.f), fmaxf(a[5],0.f));
        float pA3 = fmaxf(fmaxf(a[6],0.f), fmaxf(a[7],0.f));
        float pB0 = fmaxf(fmaxf(b[0],0.f), fmaxf(b[1],0.f));
        float pB1 = fmaxf(fmaxf(b[2],0.f), fmaxf(b[3],0.f));
        float pB2 = fmaxf(fmaxf(b[4],0.f), fmaxf(b[5],0.f));
        float pB3 = fmaxf(fmaxf(b[6],0.f), fmaxf(b[7],0.f));
        if constexpr (!MEAN) {
            int cA = 2*pr, cB = cA + 1;
            float* yrA = Y + cA*YRS + 1 + 4*q;
            float* yrB = Y + cB*YRS + 1 + 4*q;
            yrA[0]=pA0; yrA[1]=pA1; yrA[2]=pA2; yrA[3]=pA3;
            yrB[0]=pB0; yrB[1]=pB1; yrB[2]=pB2; yrB[3]=pB3;
        } else {
            float vA = (pA0+pA1) + (pA2+pA3);
            float vB = (pB0+pB1) + (pB2+pB3);
            #pragma unroll
            for (int sh = 8; sh; sh >>= 1) {     // reduce within each 16-lane half
                vA += __shfl_xor_sync(0xffffffffu, vA, sh);
                vB += __shfl_xor_sync(0xffffffffu, vB, sh);
            }
            if ((t & 15) == 0) { f3[2*pr] = vA; f3[2*pr+1] = vB; }
        }
    }
}

__global__ __launch_bounds__(NT, 1)
void encoder_kernel(const float* __restrict__ s_img, const float* __restrict__ q_img,
                    const float* __restrict__ w1, const float* __restrict__ b1,
                    const float* __restrict__ g1, const float* __restrict__ be1,
                    const float* __restrict__ m1, const float* __restrict__ v1,
                    const float* __restrict__ w2, const float* __restrict__ b2,
                    const float* __restrict__ g2, const float* __restrict__ be2,
                    const float* __restrict__ m2, const float* __restrict__ v2,
                    const float* __restrict__ w3, const float* __restrict__ b3,
                    const float* __restrict__ g3, const float* __restrict__ be3,
                    const float* __restrict__ m3, const float* __restrict__ v3,
                    const float* __restrict__ wf, const float* __restrict__ bf,
                    const float* __restrict__ gf, const float* __restrict__ bef,
                    const float* __restrict__ mf, const float* __restrict__ vf)
{
    extern __shared__ float sm[];
    const int n = blockIdx.x;
    const int t = threadIdx.x;

    float* x0  = sm + OFF_X0;
    float* s1  = sm + OFF_S1;
    float* s2  = sm + OFF_S2;
    float* w1s = sm + OFF_W1;
    float* w2s = sm + OFF_W2;
    float* w3s = sm + OFF_W3;
    float* sc1 = sm + OFF_SC1; float* bi1 = sm + OFF_BI1;
    float* sc2 = sm + OFF_SC2; float* bi2 = sm + OFF_BI2;
    float* sc3 = sm + OFF_SC3; float* bi3 = sm + OFF_BI3;
    float* scf = sm + OFF_SCF; float* bif = sm + OFF_BIF;
    float* f3  = sm + OFF_F3;
    float* red = sm + OFF_RED;

    // ---- phase A: stage input, small weights, BN fold, pads ----
    const float* inp = (n < NSUP) ? (s_img + (size_t)n*(CIN*LIN))
                                  : (q_img + (size_t)(n - NSUP)*(CIN*LIN));
    const float4* in4 = reinterpret_cast<const float4*>(inp);
    for (int e = t; e < (CIN*LIN)/4; e += NT) {
        float4 v = __ldg(in4 + e);
        int c = e >> 7;
        int l = (e & 127) << 2;
        float* xr = x0 + c*516 + 1 + l;
        xr[0]=v.x; xr[1]=v.y; xr[2]=v.z; xr[3]=v.w;
    }
    if (t < 8)  { x0[t*516]=0.f; x0[t*516+513]=0.f; x0[t*516+514]=0.f; x0[t*516+515]=0.f; }
    if (t < 32) { s1[t*260]=0.f; s1[t*260+257]=0.f; s1[t*260+258]=0.f; s1[t*260+259]=0.f; }
    if (t < 64) { s2[t*132]=0.f; s2[t*132+129]=0.f; s2[t*132+130]=0.f; s2[t*132+131]=0.f; }

    stage_w_pairs<CIN*3, 32*CIN*3>(w1, w1s, t);
    stage_w_pairs<32*3, 64*32*3>(w2, w2s, t);

    if (t < 32)  { float s = g1[t]*rsqrtf(v1[t]+EPS_BN); sc1[t]=s; bi1[t]=(b1[t]-m1[t])*s+be1[t]; }
    if (t < 64)  { float s = g2[t]*rsqrtf(v2[t]+EPS_BN); sc2[t]=s; bi2[t]=(b2[t]-m2[t])*s+be2[t]; }
    if (t < 128) {
        float s3 = g3[t]*rsqrtf(v3[t]+EPS_BN); sc3[t]=s3; bi3[t]=(b3[t]-m3[t])*s3+be3[t];
        float sF = gf[t]*rsqrtf(vf[t]+EPS_BN); scf[t]=sF; bif[t]=(bf[t]-mf[t])*sF+bef[t];
    }
    __syncthreads();

    // ---- stage 1: conv(8->32,L512) -> s1[32][256] ----
    conv_stage8<8, 32, 64, 516, false>(x0, reinterpret_cast<const ull*>(w1s),
        reinterpret_cast<const ull*>(sc1), reinterpret_cast<const ull*>(bi1),
        s1, 260, nullptr, t);
    __syncthreads();

    // ---- stage 2: conv(32->64,L256) -> s2[64][128] ----
    conv_stage8<32, 64, 32, 260, false>(s1, reinterpret_cast<const ull*>(w2s),
        reinterpret_cast<const ull*>(sc2), reinterpret_cast<const ull*>(bi2),
        s2, 132, nullptr, t);
    __syncthreads();

    // ---- phase B: stage w3 into region R (x0/s1 dead) ----
    stage_w_pairs<64*3, 128*64*3>(w3, w3s, t);
    __syncthreads();

    // ---- stage 3: conv(64->128,L128) + pool + sum -> f3[128] ----
    conv_stage8<64, 128, 16, 132, true>(s2, reinterpret_cast<const ull*>(w3s),
        reinterpret_cast<const ull*>(sc3), reinterpret_cast<const ull*>(bi3),
        nullptr, 0, f3, t);
    __syncthreads();

    // ---- stage 4: mean, FC, BN, ReLU, L2 normalize ----
    if (t < 128) f3[t] *= (1.0f/64.0f);
    __syncthreads();

    float h = 0.f;
    if (t < 128) {
        const float4* wrow = reinterpret_cast<const float4*>(wf + (size_t)t*FDIM);
        float z = 0.f;
        #pragma unroll
        for (int e = 0; e < 32; ++e) {
            float4 wv = __ldg(wrow + e);
            float4 fv = *reinterpret_cast<const float4*>(f3 + 4*e);
            z = fmaf(wv.x, fv.x, z); z = fmaf(wv.y, fv.y, z);
            z = fmaf(wv.z, fv.z, z); z = fmaf(wv.w, fv.w, z);
        }
        h = fmaxf(fmaf(z, scf[t], bif[t]), 0.f);
        float r2 = h*h;
        #pragma unroll
        for (int sh = 16; sh; sh >>= 1) r2 += __shfl_xor_sync(0xffffffffu, r2, sh);
        if ((t & 31) == 0) red[t >> 5] = r2;
    }
    __syncthreads();
    if (t == 0) {
        float s = red[0] + red[1] + red[2] + red[3];
        red[8] = 1.0f / fmaxf(sqrtf(s), 1e-12f);
    }
    __syncthreads();
    if (t < 128) g_feat[(size_t)n*FDIM + t] = h * red[8];
}

// ---- prototypes ----
__global__ __launch_bounds__(256)
void proto_kernel(const int* __restrict__ s_lab)
{
    __shared__ float proto[NWAY*FDIM];
    __shared__ float cnt[NWAY];
    const int b = blockIdx.x, t = threadIdx.x;
    for (int e = t; e < NWAY*FDIM; e += 256) proto[e] = 0.f;
    if (t < NWAY) cnt[t] = 0.f;
    __syncthreads();

    const int g = t >> 7, f = t & 127;
    for (int s = g; s < NS; s += 2) {
        int lab = __ldg(s_lab + b*NS + s);
        atomicAdd(&proto[lab*FDIM + f], g_feat[(size_t)(b*NS + s)*FDIM + f]);
    }
    for (int s = t; s < NS; s += 256) atomicAdd(&cnt[__ldg(s_lab + b*NS + s)], 1.f);
    __syncthreads();

    for (int e = t; e < NWAY*FDIM; e += 256)
        g_proto[(size_t)b*NWAY*FDIM + e] = proto[e] / cnt[e >> 7];
}

// ---- distances ----
__global__ __launch_bounds__(256)
void dist_kernel(float* __restrict__ out)
{
    __shared__ float proto[NWAY*132];
    const int b = blockIdx.x, t = threadIdx.x;
    for (int e = t; e < NWAY*FDIM; e += 256)
        proto[(e >> 7)*132 + (e & 127)] = g_proto[(size_t)b*NWAY*FDIM + e];
    __syncthreads();

    for (int pr = t; pr < NQ*NWAY; pr += 256) {
        int q = pr / NWAY, w = pr % NWAY;
        const float4* qf = reinterpret_cast<const float4*>(
            g_feat + (size_t)(NSUP + b*NQ + q)*FDIM);
        const float4* pw = reinterpret_cast<const float4*>(proto + w*132);
        float d = 0.f;
        #pragma unroll
        for (int e = 0; e < 32; ++e) {
            float4 a = __ldg(qf + e);
            float4 p = pw[e];
            float dx = a.x-p.x, dy = a.y-p.y, dz = a.z-p.z, dw = a.w-p.w;
            d = fmaf(dx,dx, fmaf(dy,dy, fmaf(dz,dz, fmaf(dw,dw, d))));
        }
        out[(size_t)b*NQ*NWAY + pr] = -sqrtf(fmaxf(d, 0.f));
    }
}

extern "C" void kernel_launch(void* const* d_in, const int* in_sizes, int n_in,
                              void* d_out, int out_size)
{
    const float* s_img = (const float*)d_in[0];
    const float* q_img = (const float*)d_in[1];
    const int*   s_lab = (const int*)  d_in[2];
    const float* w1  = (const float*)d_in[3];
    const float* b1  = (const float*)d_in[4];
    const float* g1  = (const float*)d_in[5];
    const float* be1 = (const float*)d_in[6];
    const float* m1  = (const float*)d_in[7];
    const float* v1  = (const float*)d_in[8];
    const float* w2  = (const float*)d_in[9];
    const float* b2  = (const float*)d_in[10];
    const float* g2  = (const float*)d_in[11];
    const float* be2 = (const float*)d_in[12];
    const float* m2  = (const float*)d_in[13];
    const float* v2  = (const float*)d_in[14];
    const float* w3  = (const float*)d_in[15];
    const float* b3  = (const float*)d_in[16];
    const float* g3  = (const float*)d_in[17];
    const float* be3 = (const float*)d_in[18];
    const float* m3  = (const float*)d_in[19];
    const float* v3  = (const float*)d_in[20];
    const float* wf  = (const float*)d_in[21];
    const float* bf  = (const float*)d_in[22];
    const float* gf  = (const float*)d_in[23];
    const float* bef = (const float*)d_in[24];
    const float* mf  = (const float*)d_in[25];
    const float* vf  = (const float*)d_in[26];
    float* out = (float*)d_out;

    cudaFuncSetAttribute(encoder_kernel,
                         cudaFuncAttributeMaxDynamicSharedMemorySize, SMEM_BYTES);

    encoder_kernel<<<NTOT, NT, SMEM_BYTES>>>(
        s_img, q_img,
        w1, b1, g1, be1, m1, v1,
        w2, b2, g2, be2, m2, v2,
        w3, b3, g3, be3, m3, v3,
        wf, bf, gf, bef, mf, vf);
    proto_kernel<<<B_EP, 256>>>(s_lab);
    dist_kernel<<<B_EP, 256>>>(out);
}

// round 4
// speedup vs baseline: 1.1649x; 1.1649x over previous
#include <cuda_runtime.h>
#include <math.h>

#define EPS_BN 1e-5f

// ---- problem constants ----
#define B_EP   32
#define NS     200
#define NQ     100
#define NWAY   20
#define CIN    8
#define LIN    512
#define FDIM   128
#define NSUP   (B_EP*NS)     // 6400
#define NQRY   (B_EP*NQ)     // 3200
#define NTOT   (NSUP+NQRY)   // 9600
#define NT     256           // encoder threads per CTA (2 CTAs/SM)

typedef unsigned long long ull;

// ---- device scratch (no allocs allowed) ----
__device__ float g_feat[NTOT*FDIM];
__device__ float g_proto[B_EP*NWAY*FDIM];
// pre-interleaved weights + folded BN (written once by prep_kernel)
__device__ float g_w1p[768];
__device__ float g_w2p[6144];
__device__ float g_w3p[24576];      // [2 oc-halves][pair 0..31][r 0..191][2]
__device__ float g_sc1[32],  g_bi1[32];
__device__ float g_sc2[64],  g_bi2[64];
__device__ float g_sc3[128], g_bi3[128];
__device__ float g_scf[128], g_bif[128];

// ---- shared memory layout (float offsets), total 27968 floats = 109.25KB ----
#define OFF_X0   0            // 8 x 516  = 4128
#define OFF_S1   4128         // 32 x 260 = 8320  (region [0,12448) reused by w3 half: 12288)
#define OFF_W3H  0
#define OFF_S2   12448        // 64 x 132 = 8448
#define OFF_W2   20896        // 6144
#define OFF_W1   27040        // 768
#define OFF_F3   27808        // 128
#define OFF_RED  27936        // 32
#define SMEM_FLOATS 27968
#define SMEM_BYTES  (SMEM_FLOATS*4)

// ---- packed f32x2 helpers ----
__device__ __forceinline__ ull ffma2(ull a, ull b, ull c) {
    ull d;
    asm("fma.rn.f32x2 %0, %1, %2, %3;" : "=l"(d) : "l"(a), "l"(b), "l"(c));
    return d;
}
__device__ __forceinline__ ull splat2(float x) {
    ull d;
    asm("mov.b64 %0, {%1, %1};" : "=l"(d) : "f"(x));
    return d;
}
__device__ __forceinline__ void unpack2(ull v, float& lo, float& hi) {
    asm("mov.b64 {%0, %1}, %2;" : "=f"(lo), "=f"(hi) : "l"(v));
}

// ---- one-time prep: pair-interleave conv weights, fold BN ----
__global__ __launch_bounds__(512)
void prep_kernel(const float* __restrict__ w1, const float* __restrict__ b1,
                 const float* __restrict__ g1, const float* __restrict__ be1,
                 const float* __restrict__ m1, const float* __restrict__ v1,
                 const float* __restrict__ w2, const float* __restrict__ b2,
                 const float* __restrict__ g2, const float* __restrict__ be2,
                 const float* __restrict__ m2, const float* __restrict__ v2,
                 const float* __restrict__ w3, const float* __restrict__ b3,
                 const float* __restrict__ g3, const float* __restrict__ be3,
                 const float* __restrict__ m3, const float* __restrict__ v3,
                 const float* __restrict__ bf, const float* __restrict__ gf,
                 const float* __restrict__ bef, const float* __restrict__ mf,
                 const float* __restrict__ vf)
{
    const int t = threadIdx.x;
    for (int f = t; f < 768; f += 512) {
        int o = f/24, r = f - o*24;
        g_w1p[(o>>1)*48 + 2*r + (o&1)] = w1[f];
    }
    for (int f = t; f < 6144; f += 512) {
        int o = f/96, r = f - o*96;
        g_w2p[(o>>1)*192 + 2*r + (o&1)] = w2[f];
    }
    for (int f = t; f < 24576; f += 512) {
        int o = f/192, r = f - o*192;
        int half = o >> 6, ol = o & 63;
        g_w3p[half*12288 + (ol>>1)*384 + 2*r + (ol&1)] = w3[f];
    }
    if (t < 32) {
        float s = g1[t]*rsqrtf(v1[t]+EPS_BN);
        g_sc1[t]=s; g_bi1[t]=(b1[t]-m1[t])*s+be1[t];
    } else if (t < 96) {
        int i=t-32; float s = g2[i]*rsqrtf(v2[i]+EPS_BN);
        g_sc2[i]=s; g_bi2[i]=(b2[i]-m2[i])*s+be2[i];
    } else if (t < 224) {
        int i=t-96; float s = g3[i]*rsqrtf(v3[i]+EPS_BN);
        g_sc3[i]=s; g_bi3[i]=(b3[i]-m3[i])*s+be3[i];
    } else if (t < 352) {
        int i=t-224; float s = gf[i]*rsqrtf(vf[i]+EPS_BN);
        g_scf[i]=s; g_bif[i]=(bf[i]-mf[i])*s+bef[i];
    }
}

// Fused conv1d(k=3,pad=1)+BN+ReLU+maxpool2, packed f32x2.
// Tile: 4 out channels (2 pairs) x 8 conv positions per thread.
// co = output-channel offset (stage-3 OC halves). BN scale/bias read from
// global pair arrays via __ldg.
template<int IC, int OC, int Q, int XRS, bool MEAN>
__device__ __forceinline__ void conv_stage8(const float* __restrict__ X,
                                            const ull* __restrict__ Wp,
                                            const ull* __restrict__ scp,
                                            const ull* __restrict__ bip,
                                            int co,
                                            float* __restrict__ Y, int YRS,
                                            float* __restrict__ f3, int t)
{
    constexpr int IC3 = IC*3;
    constexpr int NIT = (OC/4)*Q/NT;
    #pragma unroll
    for (int it = 0; it < NIT; ++it) {
        int T  = it*NT + t;
        int q  = T % Q;
        int ot = T / Q;
        int l0 = 8*q, o0 = 4*ot;

        ull acc[2][8];
        #pragma unroll
        for (int p = 0; p < 2; ++p)
            #pragma unroll
            for (int j = 0; j < 8; ++j) acc[p][j] = 0ull;

        const ull* w0r = Wp + (o0 >> 1)*IC3;
        const ull* w1r = w0r + IC3;
        const float* xcol = X + l0;
        #pragma unroll 4
        for (int i = 0; i < IC; ++i) {
            const float* xr = xcol + i*XRS;
            float4 xa = *reinterpret_cast<const float4*>(xr);
            float4 xb = *reinterpret_cast<const float4*>(xr + 4);
            float2 xc = *reinterpret_cast<const float2*>(xr + 8);
            ull xs[10];
            xs[0]=splat2(xa.x); xs[1]=splat2(xa.y); xs[2]=splat2(xa.z); xs[3]=splat2(xa.w);
            xs[4]=splat2(xb.x); xs[5]=splat2(xb.y); xs[6]=splat2(xb.z); xs[7]=splat2(xb.w);
            xs[8]=splat2(xc.x); xs[9]=splat2(xc.y);
            ull wa0 = w0r[3*i], wa1 = w0r[3*i+1], wa2 = w0r[3*i+2];
            ull wb0 = w1r[3*i], wb1 = w1r[3*i+1], wb2 = w1r[3*i+2];
            #pragma unroll
            for (int j = 0; j < 8; ++j) {
                acc[0][j] = ffma2(wa2, xs[j+2], ffma2(wa1, xs[j+1], ffma2(wa0, xs[j], acc[0][j])));
                acc[1][j] = ffma2(wb2, xs[j+2], ffma2(wb1, xs[j+1], ffma2(wb0, xs[j], acc[1][j])));
            }
        }

        #pragma unroll
        for (int p = 0; p < 2; ++p) {
            int prl = (o0 >> 1) + p;              // local pair
            int prg = (co >> 1) + prl;            // global pair for BN
            ull s2 = __ldg(scp + prg), b2 = __ldg(bip + prg);
            float a[8], b[8];
            #pragma unroll
            for (int j = 0; j < 8; ++j) {
                ull y = ffma2(acc[p][j], s2, b2);
                unpack2(y, a[j], b[j]);
            }
            float pA0 = fmaxf(fmaxf(a[0],0.f), fmaxf(a[1],0.f));
            float pA1 = fmaxf(fmaxf(a[2],0.f), fmaxf(a[3],0.f));
            float pA2 = fmaxf(fmaxf(a[4],0.f), fmaxf(a[5],0.f));
            float pA3 = fmaxf(fmaxf(a[6],0.f), fmaxf(a[7],0.f));
            float pB0 = fmaxf(fmaxf(b[0],0.f), fmaxf(b[1],0.f));
            float pB1 = fmaxf(fmaxf(b[2],0.f), fmaxf(b[3],0.f));
            float pB2 = fmaxf(fmaxf(b[4],0.f), fmaxf(b[5],0.f));
            float pB3 = fmaxf(fmaxf(b[6],0.f), fmaxf(b[7],0.f));
            if constexpr (!MEAN) {
                int cA = 2*prl, cB = cA + 1;
                float* yrA = Y + cA*YRS + 1 + 4*q;
                float* yrB = Y + cB*YRS + 1 + 4*q;
                yrA[0]=pA0; yrA[1]=pA1; yrA[2]=pA2; yrA[3]=pA3;
                yrB[0]=pB0; yrB[1]=pB1; yrB[2]=pB2; yrB[3]=pB3;
            } else {
                float vA = (pA0+pA1) + (pA2+pA3);
                float vB = (pB0+pB1) + (pB2+pB3);
                #pragma unroll
                for (int sh = 8; sh; sh >>= 1) {     // reduce within 16-lane half
                    vA += __shfl_xor_sync(0xffffffffu, vA, sh);
                    vB += __shfl_xor_sync(0xffffffffu, vB, sh);
                }
                if ((t & 15) == 0) { f3[co + 2*prl] = vA; f3[co + 2*prl + 1] = vB; }
            }
        }
    }
}

__global__ __launch_bounds__(NT, 2)
void encoder_kernel(const float* __restrict__ s_img, const float* __restrict__ q_img,
                    const float* __restrict__ wf)
{
    extern __shared__ float sm[];
    const int n = blockIdx.x;
    const int t = threadIdx.x;

    float* x0  = sm + OFF_X0;
    float* s1  = sm + OFF_S1;
    float* w3h = sm + OFF_W3H;
    float* s2  = sm + OFF_S2;
    float* w2s = sm + OFF_W2;
    float* w1s = sm + OFF_W1;
    float* f3  = sm + OFF_F3;
    float* red = sm + OFF_RED;

    // ---- phase A: stage input + pair-interleaved w1/w2, zero pads ----
    const float* inp = (n < NSUP) ? (s_img + (size_t)n*(CIN*LIN))
                                  : (q_img + (size_t)(n - NSUP)*(CIN*LIN));
    const float4* in4 = reinterpret_cast<const float4*>(inp);
    for (int e = t; e < (CIN*LIN)/4; e += NT) {
        float4 v = __ldg(in4 + e);
        int c = e >> 7;
        int l = (e & 127) << 2;
        float* xr = x0 + c*516 + 1 + l;
        xr[0]=v.x; xr[1]=v.y; xr[2]=v.z; xr[3]=v.w;
    }
    if (t < 8)  { x0[t*516]=0.f; x0[t*516+513]=0.f; x0[t*516+514]=0.f; x0[t*516+515]=0.f; }
    if (t < 32) { s1[t*260]=0.f; s1[t*260+257]=0.f; s1[t*260+258]=0.f; s1[t*260+259]=0.f; }
    if (t < 64) { s2[t*132]=0.f; s2[t*132+129]=0.f; s2[t*132+130]=0.f; s2[t*132+131]=0.f; }

    {   // contiguous float4 copies of pre-interleaved weights
        const float4* g1p = reinterpret_cast<const float4*>(g_w1p);
        if (t < 192) reinterpret_cast<float4*>(w1s)[t] = __ldg(g1p + t);
        const float4* g2p = reinterpret_cast<const float4*>(g_w2p);
        for (int e = t; e < 1536; e += NT)
            reinterpret_cast<float4*>(w2s)[e] = __ldg(g2p + e);
    }
    __syncthreads();

    // ---- stage 1: conv(8->32,L512) -> s1[32][256] ----
    conv_stage8<8, 32, 64, 516, false>(x0, reinterpret_cast<const ull*>(w1s),
        reinterpret_cast<const ull*>(g_sc1), reinterpret_cast<const ull*>(g_bi1),
        0, s1, 260, nullptr, t);
    __syncthreads();

    // ---- stage 2: conv(32->64,L256) -> s2[64][128] ----
    conv_stage8<32, 64, 32, 260, false>(s1, reinterpret_cast<const ull*>(w2s),
        reinterpret_cast<const ull*>(g_sc2), reinterpret_cast<const ull*>(g_bi2),
        0, s2, 132, nullptr, t);
    __syncthreads();

    // ---- stage 3: conv(64->128,L128)+pool+sum -> f3, two OC halves ----
    #pragma unroll
    for (int h = 0; h < 2; ++h) {
        const float4* g3p = reinterpret_cast<const float4*>(g_w3p + h*12288);
        for (int e = t; e < 3072; e += NT)
            reinterpret_cast<float4*>(w3h)[e] = __ldg(g3p + e);
        __syncthreads();
        conv_stage8<64, 64, 16, 132, true>(s2, reinterpret_cast<const ull*>(w3h),
            reinterpret_cast<const ull*>(g_sc3), reinterpret_cast<const ull*>(g_bi3),
            64*h, nullptr, 0, f3, t);
        __syncthreads();
    }

    // ---- stage 4: mean, FC, BN, ReLU, L2 normalize ----
    if (t < 128) f3[t] *= (1.0f/64.0f);
    __syncthreads();

    float hval = 0.f;
    if (t < 128) {
        const float4* wrow = reinterpret_cast<const float4*>(wf + (size_t)t*FDIM);
        float z = 0.f;
        #pragma unroll
        for (int e = 0; e < 32; ++e) {
            float4 wv = __ldg(wrow + e);
            float4 fv = *reinterpret_cast<const float4*>(f3 + 4*e);
            z = fmaf(wv.x, fv.x, z); z = fmaf(wv.y, fv.y, z);
            z = fmaf(wv.z, fv.z, z); z = fmaf(wv.w, fv.w, z);
        }
        hval = fmaxf(fmaf(z, __ldg(g_scf + t), __ldg(g_bif + t)), 0.f);
        float r2 = hval*hval;
        #pragma unroll
        for (int sh = 16; sh; sh >>= 1) r2 += __shfl_xor_sync(0xffffffffu, r2, sh);
        if ((t & 31) == 0) red[t >> 5] = r2;
    }
    __syncthreads();
    if (t == 0) {
        float s = red[0] + red[1] + red[2] + red[3];
        red[8] = 1.0f / fmaxf(sqrtf(s), 1e-12f);
    }
    __syncthreads();
    if (t < 128) g_feat[(size_t)n*FDIM + t] = hval * red[8];
}

// ---- prototypes ----
__global__ __launch_bounds__(256)
void proto_kernel(const int* __restrict__ s_lab)
{
    __shared__ float proto[NWAY*FDIM];
    __shared__ float cnt[NWAY];
    const int b = blockIdx.x, t = threadIdx.x;
    for (int e = t; e < NWAY*FDIM; e += 256) proto[e] = 0.f;
    if (t < NWAY) cnt[t] = 0.f;
    __syncthreads();

    const int g = t >> 7, f = t & 127;
    for (int s = g; s < NS; s += 2) {
        int lab = __ldg(s_lab + b*NS + s);
        atomicAdd(&proto[lab*FDIM + f], g_feat[(size_t)(b*NS + s)*FDIM + f]);
    }
    for (int s = t; s < NS; s += 256) atomicAdd(&cnt[__ldg(s_lab + b*NS + s)], 1.f);
    __syncthreads();

    for (int e = t; e < NWAY*FDIM; e += 256)
        g_proto[(size_t)b*NWAY*FDIM + e] = proto[e] / cnt[e >> 7];
}

// ---- distances ----
__global__ __launch_bounds__(256)
void dist_kernel(float* __restrict__ out)
{
    __shared__ float proto[NWAY*132];
    const int b = blockIdx.x, t = threadIdx.x;
    for (int e = t; e < NWAY*FDIM; e += 256)
        proto[(e >> 7)*132 + (e & 127)] = g_proto[(size_t)b*NWAY*FDIM + e];
    __syncthreads();

    for (int pr = t; pr < NQ*NWAY; pr += 256) {
        int q = pr / NWAY, w = pr % NWAY;
        const float4* qf = reinterpret_cast<const float4*>(
            g_feat + (size_t)(NSUP + b*NQ + q)*FDIM);
        const float4* pw = reinterpret_cast<const float4*>(proto + w*132);
        float d = 0.f;
        #pragma unroll
        for (int e = 0; e < 32; ++e) {
            float4 a = __ldg(qf + e);
            float4 p = pw[e];
            float dx = a.x-p.x, dy = a.y-p.y, dz = a.z-p.z, dw = a.w-p.w;
            d = fmaf(dx,dx, fmaf(dy,dy, fmaf(dz,dz, fmaf(dw,dw, d))));
        }
        out[(size_t)b*NQ*NWAY + pr] = -sqrtf(fmaxf(d, 0.f));
    }
}

extern "C" void kernel_launch(void* const* d_in, const int* in_sizes, int n_in,
                              void* d_out, int out_size)
{
    const float* s_img = (const float*)d_in[0];
    const float* q_img = (const float*)d_in[1];
    const int*   s_lab = (const int*)  d_in[2];
    const float* w1  = (const float*)d_in[3];
    const float* b1  = (const float*)d_in[4];
    const float* g1  = (const float*)d_in[5];
    const float* be1 = (const float*)d_in[6];
    const float* m1  = (const float*)d_in[7];
    const float* v1  = (const float*)d_in[8];
    const float* w2  = (const float*)d_in[9];
    const float* b2  = (const float*)d_in[10];
    const float* g2  = (const float*)d_in[11];
    const float* be2 = (const float*)d_in[12];
    const float* m2  = (const float*)d_in[13];
    const float* v2  = (const float*)d_in[14];
    const float* w3  = (const float*)d_in[15];
    const float* b3  = (const float*)d_in[16];
    const float* g3  = (const float*)d_in[17];
    const float* be3 = (const float*)d_in[18];
    const float* m3  = (const float*)d_in[19];
    const float* v3  = (const float*)d_in[20];
    const float* wf  = (const float*)d_in[21];
    const float* bf  = (const float*)d_in[22];
    const float* gf  = (const float*)d_in[23];
    const float* bef = (const float*)d_in[24];
    const float* mf  = (const float*)d_in[25];
    const float* vf  = (const float*)d_in[26];
    float* out = (float*)d_out;

    cudaFuncSetAttribute(encoder_kernel,
                         cudaFuncAttributeMaxDynamicSharedMemorySize, SMEM_BYTES);

    prep_kernel<<<1, 512>>>(w1, b1, g1, be1, m1, v1,
                            w2, b2, g2, be2, m2, v2,
                            w3, b3, g3, be3, m3, v3,
                            bf, gf, bef, mf, vf);
    encoder_kernel<<<NTOT, NT, SMEM_BYTES>>>(s_img, q_img, wf);
    proto_kernel<<<B_EP, 256>>>(s_lab);
    dist_kernel<<<B_EP, 256>>>(out);
}